// round 3
// baseline (speedup 1.0000x reference)
#include <cuda_runtime.h>
#include <cstdint>

// 3-level db4 wavedec (periodization) along axis 1 of (64, 4096, 64) fp32.
// Output rows: [cA3 (512) | cD3 (512) | cD2 (1024) | cD1 (2048)] x 64 feats.
//
// R3: 256-thread blocks, __launch_bounds__(256,6) -> 6 CTAs/SM (75% occ).
// Streaming accumulation (one row load at a time into 8 persistent
// accumulators) keeps register count <= 42 without spills.

#define NTHREADS 256
#define A1_ROWS  82   // valid local cA1 rows
#define A2_ROWS  38   // valid local cA2 rows
#define A1_CAP   88
#define A2_CAP   40

__device__ __forceinline__ float2 f2fma(float2 w, float c, float2 acc) {
    acc.x = fmaf(w.x, c, acc.x);
    acc.y = fmaf(w.y, c, acc.y);
    return acc;
}

// Reversed db4 filters: out[i] = sum_t src[2i + t] * R*[t]
#define DECL_FILTERS                                                          \
    const float RLO[8] = {                                                    \
         0.23037781330885523f,  0.7148465705525415f,   0.6308807679295904f,   \
        -0.02798376941698385f, -0.18703481171888114f,  0.030841381835986965f, \
         0.032883011666982945f, -0.010597401784997278f };                     \
    const float RHI[8] = {                                                    \
        -0.010597401784997278f, -0.032883011666982945f, 0.030841381835986965f,\
         0.18703481171888114f,  -0.02798376941698385f, -0.6308807679295904f,  \
         0.7148465705525415f,   -0.23037781330885523f };

// accumulate row t (of the 14-row window) into the 4 output accumulators
#define ACC_STEP(w, T)                                    \
    {                                                     \
        _Pragma("unroll")                                 \
        for (int q = 0; q < 4; ++q) {                     \
            const int tt = (T) - 2 * q;                   \
            if (tt >= 0 && tt < 8) {                      \
                a[q] = f2fma((w), RLO[tt], a[q]);         \
                d[q] = f2fma((w), RHI[tt], d[q]);         \
            }                                             \
        }                                                 \
    }

__global__ void __launch_bounds__(NTHREADS, 6)
wavedec_kernel(const float* __restrict__ x, float* __restrict__ out) {
    __shared__ float2 s_a1[A1_CAP * 32];
    __shared__ float2 s_a2[A2_CAP * 32];

    const int tid  = threadIdx.x;
    const int f2   = tid & 31;    // float2 feature lane
    const int grp  = tid >> 5;    // 0..7, each group: 4 consecutive rows/pass
    const int tile = blockIdx.x;  // 0..31
    const int b    = blockIdx.y;  // 0..63

    const float2* __restrict__ xb2 =
        reinterpret_cast<const float2*>(x + (size_t)b * 4096 * 64);
    float2* __restrict__ ob2 =
        reinterpret_cast<float2*>(out + (size_t)b * 4096 * 64);

    const int g0 = 128 * tile - 42;  // global x row of local window origin

    // ---- Level 1: x (global) -> cA1 (smem) + cD1 (global) ----
#pragma unroll
    for (int pass = 0; pass < 3; ++pass) {
        const int i0 = pass * 32 + grp * 4;
        if (i0 < A1_ROWS) {
            DECL_FILTERS
            float2 a[4] = {}, d[4] = {};
            const int r0 = g0 + 2 * i0;
            if (r0 >= 0 && r0 <= 4096 - 14) {
                const float2* p = xb2 + (size_t)r0 * 32 + f2;
#pragma unroll
                for (int t = 0; t < 14; ++t) {
                    const float2 w = p[t * 32];
                    ACC_STEP(w, t)
                }
            } else {
#pragma unroll
                for (int t = 0; t < 14; ++t) {
                    const int r = (r0 + t + 4096) & 4095;
                    const float2 w = xb2[(size_t)r * 32 + f2];
                    ACC_STEP(w, t)
                }
            }
#pragma unroll
            for (int q = 0; q < 4; ++q) {
                const int i = i0 + q;          // max 83 < A1_CAP
                s_a1[i * 32 + f2] = a[q];
                if (i >= 18 && i < A1_ROWS)
                    ob2[(size_t)(2048 + 64 * tile + (i - 18)) * 32 + f2] = d[q];
            }
        }
    }
    __syncthreads();

    // ---- Level 2: cA1 (smem) -> cA2 (smem) + cD2 (global) ----
#pragma unroll
    for (int pass = 0; pass < 2; ++pass) {
        const int i0 = pass * 32 + grp * 4;
        if (i0 < A2_ROWS) {
            DECL_FILTERS
            float2 a[4] = {}, d[4] = {};
            const float2* p = s_a1 + 2 * i0 * 32 + f2;
#pragma unroll
            for (int t = 0; t < 14; ++t) {
                const float2 w = p[t * 32];
                ACC_STEP(w, t)
            }
#pragma unroll
            for (int q = 0; q < 4; ++q) {
                const int i = i0 + q;          // max 39 < A2_CAP
                s_a2[i * 32 + f2] = a[q];
                if (i >= 6 && i < A2_ROWS)
                    ob2[(size_t)(1024 + 32 * tile + (i - 6)) * 32 + f2] = d[q];
            }
        }
    }
    __syncthreads();

    // ---- Level 3: cA2 (smem) -> cA3 + cD3 (global) ----
    {
        const int i0 = grp * 4;
        if (i0 < 16) {
            DECL_FILTERS
            float2 a[4] = {}, d[4] = {};
            const float2* p = s_a2 + 2 * i0 * 32 + f2;
#pragma unroll
            for (int t = 0; t < 14; ++t) {
                const float2 w = p[t * 32];
                ACC_STEP(w, t)
            }
#pragma unroll
            for (int q = 0; q < 4; ++q) {
                const int i = i0 + q;
                ob2[(size_t)(16 * tile + i) * 32 + f2]       = a[q];
                ob2[(size_t)(512 + 16 * tile + i) * 32 + f2] = d[q];
            }
        }
    }
}

extern "C" void kernel_launch(void* const* d_in, const int* in_sizes, int n_in,
                              void* d_out, int out_size) {
    const float* x = (const float*)d_in[0];
    float* out = (float*)d_out;
    dim3 grid(32, 64);
    wavedec_kernel<<<grid, NTHREADS>>>(x, out);
}

// round 4
// speedup vs baseline: 1.1404x; 1.1404x over previous
#include <cuda_runtime.h>
#include <cstdint>

// 3-level db4 wavedec (periodization) along axis 1 of (64, 4096, 64) fp32.
// Output rows: [cA3 (512) | cD3 (512) | cD2 (1024) | cD1 (2048)] x 64 feats.
//
// R4: packed f32x2 FMA (fma.rn.f32x2) + 128-bit memory ops. Each thread owns
// 4 features; 16 lanes cover a 64-float row. Halves both FFMA and memory
// instruction issue vs the float2 version.

#define NTHREADS 256
#define A1_ROWS  82   // valid local cA1 rows
#define A2_ROWS  38   // valid local cA2 rows
#define A1_CAP   88
#define A2_CAP   40

__device__ __forceinline__ void fma2(unsigned long long& acc,
                                     unsigned long long w,
                                     unsigned long long c) {
    asm("fma.rn.f32x2 %0, %1, %2, %0;" : "+l"(acc) : "l"(w), "l"(c));
}

// accumulate window row T into the 4-row output accumulators
#define ACC4(WL, WH, T)                                   \
    {                                                     \
        _Pragma("unroll")                                 \
        for (int q = 0; q < 4; ++q) {                     \
            const int tt = (T) - 2 * q;                   \
            if (tt >= 0 && tt < 8) {                      \
                fma2(aL[q], (WL), clo[tt]);               \
                fma2(aH[q], (WH), clo[tt]);               \
                fma2(dL[q], (WL), chi[tt]);               \
                fma2(dH[q], (WH), chi[tt]);               \
            }                                             \
        }                                                 \
    }

__global__ void __launch_bounds__(NTHREADS, 3)
wavedec_kernel(const float* __restrict__ x, float* __restrict__ out) {
    __shared__ ulonglong2 s_a1[A1_CAP * 16];
    __shared__ ulonglong2 s_a2[A2_CAP * 16];

    const int tid  = threadIdx.x;
    const int f4   = tid & 15;    // float4 feature lane (64 floats = 16 float4)
    const int grp  = tid >> 4;    // 0..15, each group: 4 consecutive rows/pass
    const int tile = blockIdx.x;  // 0..31
    const int b    = blockIdx.y;  // 0..63

    // Reversed db4 filters: out[i] = sum_t src[2i+t] * R*[t]
    const float RLO[8] = {
         0.23037781330885523f,  0.7148465705525415f,   0.6308807679295904f,
        -0.02798376941698385f, -0.18703481171888114f,  0.030841381835986965f,
         0.032883011666982945f, -0.010597401784997278f };
    const float RHI[8] = {
        -0.010597401784997278f, -0.032883011666982945f, 0.030841381835986965f,
         0.18703481171888114f,  -0.02798376941698385f, -0.6308807679295904f,
         0.7148465705525415f,   -0.23037781330885523f };

    // pack each coefficient into both f32 lanes of a 64-bit reg
    unsigned long long clo[8], chi[8];
#pragma unroll
    for (int t = 0; t < 8; ++t) {
        clo[t] = (unsigned long long)__float_as_uint(RLO[t]) * 0x100000001ull;
        chi[t] = (unsigned long long)__float_as_uint(RHI[t]) * 0x100000001ull;
    }

    const ulonglong2* __restrict__ xb4 =
        reinterpret_cast<const ulonglong2*>(x + (size_t)b * 4096 * 64);
    ulonglong2* __restrict__ ob4 =
        reinterpret_cast<ulonglong2*>(out + (size_t)b * 4096 * 64);

    const int g0 = 128 * tile - 42;  // global x row of local window origin

    // ---- Level 1: x (global) -> cA1 (smem) + cD1 (global) ----
#pragma unroll
    for (int pass = 0; pass < 2; ++pass) {
        const int i0 = pass * 64 + grp * 4;
        if (i0 < A1_ROWS) {
            unsigned long long aL[4] = {}, aH[4] = {}, dL[4] = {}, dH[4] = {};
            const int r0 = g0 + 2 * i0;
            if (r0 >= 0 && r0 <= 4096 - 14) {
                const ulonglong2* p = xb4 + (size_t)r0 * 16 + f4;
#pragma unroll
                for (int t = 0; t < 14; ++t) {
                    const ulonglong2 w = p[t * 16];
                    ACC4(w.x, w.y, t)
                }
            } else {
#pragma unroll
                for (int t = 0; t < 14; ++t) {
                    const int r = (r0 + t + 4096) & 4095;
                    const ulonglong2 w = xb4[(size_t)r * 16 + f4];
                    ACC4(w.x, w.y, t)
                }
            }
#pragma unroll
            for (int q = 0; q < 4; ++q) {
                const int i = i0 + q;          // max 83 < A1_CAP
                s_a1[i * 16 + f4] = make_ulonglong2(aL[q], aH[q]);
                if (i >= 18 && i < A1_ROWS)
                    ob4[(size_t)(2048 + 64 * tile + (i - 18)) * 16 + f4] =
                        make_ulonglong2(dL[q], dH[q]);
            }
        }
    }
    __syncthreads();

    // ---- Level 2: cA1 (smem) -> cA2 (smem) + cD2 (global) ----
    {
        const int i0 = grp * 4;
        if (i0 < A2_ROWS) {
            unsigned long long aL[4] = {}, aH[4] = {}, dL[4] = {}, dH[4] = {};
            const ulonglong2* p = s_a1 + 2 * i0 * 16 + f4;
#pragma unroll
            for (int t = 0; t < 14; ++t) {
                const ulonglong2 w = p[t * 16];
                ACC4(w.x, w.y, t)
            }
#pragma unroll
            for (int q = 0; q < 4; ++q) {
                const int i = i0 + q;          // max 39 < A2_CAP
                s_a2[i * 16 + f4] = make_ulonglong2(aL[q], aH[q]);
                if (i >= 6 && i < A2_ROWS)
                    ob4[(size_t)(1024 + 32 * tile + (i - 6)) * 16 + f4] =
                        make_ulonglong2(dL[q], dH[q]);
            }
        }
    }
    __syncthreads();

    // ---- Level 3: cA2 (smem) -> cA3 + cD3 (global) ----
    {
        const int i0 = grp * 4;
        if (i0 < 16) {
            unsigned long long aL[4] = {}, aH[4] = {}, dL[4] = {}, dH[4] = {};
            const ulonglong2* p = s_a2 + 2 * i0 * 16 + f4;
#pragma unroll
            for (int t = 0; t < 14; ++t) {
                const ulonglong2 w = p[t * 16];
                ACC4(w.x, w.y, t)
            }
#pragma unroll
            for (int q = 0; q < 4; ++q) {
                const int i = i0 + q;
                ob4[(size_t)(16 * tile + i) * 16 + f4] =
                    make_ulonglong2(aL[q], aH[q]);
                ob4[(size_t)(512 + 16 * tile + i) * 16 + f4] =
                    make_ulonglong2(dL[q], dH[q]);
            }
        }
    }
}

extern "C" void kernel_launch(void* const* d_in, const int* in_sizes, int n_in,
                              void* d_out, int out_size) {
    const float* x = (const float*)d_in[0];
    float* out = (float*)d_out;
    dim3 grid(32, 64);
    wavedec_kernel<<<grid, NTHREADS>>>(x, out);
}

// round 5
// speedup vs baseline: 1.1484x; 1.0071x over previous
#include <cuda_runtime.h>
#include <cstdint>

// 3-level db4 wavedec (periodization) along axis 1 of (64, 4096, 64) fp32.
// Output rows: [cA3 (512) | cD3 (512) | cD2 (1024) | cD1 (2048)] x 64 feats.
//
// R5: packed f32x2 FMA + 128-bit memory ops (as R4), but the detail filter
// reuses the approx-filter registers via RHI[t] = s(t)*RLO[7-t] (sign uniform
// per loaded row), cutting 16 constant regs -> 4 CTAs/SM.

#define NTHREADS 256
#define A1_ROWS  82   // valid local cA1 rows
#define A2_ROWS  38   // valid local cA2 rows
#define A1_CAP   88
#define A2_CAP   40

__device__ __forceinline__ void fma2(unsigned long long& acc,
                                     unsigned long long w,
                                     unsigned long long c) {
    asm("fma.rn.f32x2 %0, %1, %2, %0;" : "+l"(acc) : "l"(w), "l"(c));
}

__device__ __forceinline__ unsigned long long pneg(unsigned long long v) {
    return v ^ 0x8000000080000000ull;
}

// accumulate window row T into the 4-row output accumulators.
// a[q] += w * RLO[tt];  d[q] += (s(T)*w) * RLO[7-tt],  tt = T - 2q.
#define ACC4(WL, WH, T)                                             \
    {                                                               \
        const unsigned long long nWL = ((T) & 1) ? pneg(WL) : (WL); \
        const unsigned long long nWH = ((T) & 1) ? pneg(WH) : (WH); \
        _Pragma("unroll")                                           \
        for (int q = 0; q < 4; ++q) {                               \
            const int tt = (T) - 2 * q;                             \
            if (tt >= 0 && tt < 8) {                                \
                fma2(aL[q], (WL), clo[tt]);                         \
                fma2(aH[q], (WH), clo[tt]);                         \
                fma2(dL[q], nWL, clo[7 - tt]);                      \
                fma2(dH[q], nWH, clo[7 - tt]);                      \
            }                                                       \
        }                                                           \
    }

__global__ void __launch_bounds__(NTHREADS, 4)
wavedec_kernel(const float* __restrict__ x, float* __restrict__ out) {
    __shared__ ulonglong2 s_a1[A1_CAP * 16];
    __shared__ ulonglong2 s_a2[A2_CAP * 16];

    const int tid  = threadIdx.x;
    const int f4   = tid & 15;    // float4 feature lane (64 floats = 16 float4)
    const int grp  = tid >> 4;    // 0..15, each group: 4 consecutive rows/pass
    const int tile = blockIdx.x;  // 0..31
    const int b    = blockIdx.y;  // 0..63

    // Reversed approx filter: out_a[i] = sum_t src[2i+t] * RLO[t]
    const float RLO[8] = {
         0.23037781330885523f,  0.7148465705525415f,   0.6308807679295904f,
        -0.02798376941698385f, -0.18703481171888114f,  0.030841381835986965f,
         0.032883011666982945f, -0.010597401784997278f };

    unsigned long long clo[8];
#pragma unroll
    for (int t = 0; t < 8; ++t)
        clo[t] = (unsigned long long)__float_as_uint(RLO[t]) * 0x100000001ull;

    const ulonglong2* __restrict__ xb4 =
        reinterpret_cast<const ulonglong2*>(x + (size_t)b * 4096 * 64);
    ulonglong2* __restrict__ ob4 =
        reinterpret_cast<ulonglong2*>(out + (size_t)b * 4096 * 64);

    const int g0 = 128 * tile - 42;  // global x row of local window origin

    // ---- Level 1: x (global) -> cA1 (smem) + cD1 (global) ----
#pragma unroll
    for (int pass = 0; pass < 2; ++pass) {
        const int i0 = pass * 64 + grp * 4;
        if (i0 < A1_ROWS) {
            unsigned long long aL[4] = {}, aH[4] = {}, dL[4] = {}, dH[4] = {};
            const int r0 = g0 + 2 * i0;
            if (r0 >= 0 && r0 <= 4096 - 14) {
                const ulonglong2* p = xb4 + (size_t)r0 * 16 + f4;
#pragma unroll
                for (int t = 0; t < 14; ++t) {
                    const ulonglong2 w = p[t * 16];
                    ACC4(w.x, w.y, t)
                }
            } else {
#pragma unroll
                for (int t = 0; t < 14; ++t) {
                    const int r = (r0 + t + 4096) & 4095;
                    const ulonglong2 w = xb4[(size_t)r * 16 + f4];
                    ACC4(w.x, w.y, t)
                }
            }
#pragma unroll
            for (int q = 0; q < 4; ++q) {
                const int i = i0 + q;          // max 83 < A1_CAP
                s_a1[i * 16 + f4] = make_ulonglong2(aL[q], aH[q]);
                if (i >= 18 && i < A1_ROWS)
                    ob4[(size_t)(2048 + 64 * tile + (i - 18)) * 16 + f4] =
                        make_ulonglong2(dL[q], dH[q]);
            }
        }
    }
    __syncthreads();

    // ---- Level 2: cA1 (smem) -> cA2 (smem) + cD2 (global) ----
    {
        const int i0 = grp * 4;
        if (i0 < A2_ROWS) {
            unsigned long long aL[4] = {}, aH[4] = {}, dL[4] = {}, dH[4] = {};
            const ulonglong2* p = s_a1 + 2 * i0 * 16 + f4;
#pragma unroll
            for (int t = 0; t < 14; ++t) {
                const ulonglong2 w = p[t * 16];
                ACC4(w.x, w.y, t)
            }
#pragma unroll
            for (int q = 0; q < 4; ++q) {
                const int i = i0 + q;          // max 39 < A2_CAP
                s_a2[i * 16 + f4] = make_ulonglong2(aL[q], aH[q]);
                if (i >= 6 && i < A2_ROWS)
                    ob4[(size_t)(1024 + 32 * tile + (i - 6)) * 16 + f4] =
                        make_ulonglong2(dL[q], dH[q]);
            }
        }
    }
    __syncthreads();

    // ---- Level 3: cA2 (smem) -> cA3 + cD3 (global) ----
    {
        const int i0 = grp * 4;
        if (i0 < 16) {
            unsigned long long aL[4] = {}, aH[4] = {}, dL[4] = {}, dH[4] = {};
            const ulonglong2* p = s_a2 + 2 * i0 * 16 + f4;
#pragma unroll
            for (int t = 0; t < 14; ++t) {
                const ulonglong2 w = p[t * 16];
                ACC4(w.x, w.y, t)
            }
#pragma unroll
            for (int q = 0; q < 4; ++q) {
                const int i = i0 + q;
                ob4[(size_t)(16 * tile + i) * 16 + f4] =
                    make_ulonglong2(aL[q], aH[q]);
                ob4[(size_t)(512 + 16 * tile + i) * 16 + f4] =
                    make_ulonglong2(dL[q], dH[q]);
            }
        }
    }
}

extern "C" void kernel_launch(void* const* d_in, const int* in_sizes, int n_in,
                              void* d_out, int out_size) {
    const float* x = (const float*)d_in[0];
    float* out = (float*)d_out;
    dim3 grid(32, 64);
    wavedec_kernel<<<grid, NTHREADS>>>(x, out);
}

// round 6
// speedup vs baseline: 1.1511x; 1.0024x over previous
#include <cuda_runtime.h>
#include <cstdint>

// 3-level db4 wavedec (periodization) along axis 1 of (64, 4096, 64) fp32.
// Output rows: [cA3 (512) | cD3 (512) | cD2 (1024) | cD1 (2048)] x 64 feats.
//
// R6: packed f32x2 FMA + 128-bit memory ops + register-diet detail filter
// (RHI[t] = s(t)*RLO[7-t]) as R5, but with R4's *batched* 14-row window
// loads restored at every level (MLP ~14 instead of ~2). lb(256,3) gives
// ptxas enough registers to keep the whole window in flight.

#define NTHREADS 256
#define A1_ROWS  82   // valid local cA1 rows
#define A2_ROWS  38   // valid local cA2 rows
#define A1_CAP   88
#define A2_CAP   40

__device__ __forceinline__ void fma2(unsigned long long& acc,
                                     unsigned long long w,
                                     unsigned long long c) {
    asm("fma.rn.f32x2 %0, %1, %2, %0;" : "+l"(acc) : "l"(w), "l"(c));
}

__device__ __forceinline__ unsigned long long pneg(unsigned long long v) {
    return v ^ 0x8000000080000000ull;
}

// consume batched window v[14] into 4-row accumulators:
// a[q] += v[2q+t]*RLO[t];  d[q] += s(t)*v[2q+t]*RLO[7-t]
#define CONSUME_WINDOW                                              \
    _Pragma("unroll")                                               \
    for (int t = 0; t < 14; ++t) {                                  \
        const unsigned long long WL = v[t].x, WH = v[t].y;          \
        const unsigned long long nWL = (t & 1) ? pneg(WL) : WL;     \
        const unsigned long long nWH = (t & 1) ? pneg(WH) : WH;     \
        _Pragma("unroll")                                           \
        for (int q = 0; q < 4; ++q) {                               \
            const int tt = t - 2 * q;                               \
            if (tt >= 0 && tt < 8) {                                \
                fma2(aL[q], WL, clo[tt]);                           \
                fma2(aH[q], WH, clo[tt]);                           \
                fma2(dL[q], nWL, clo[7 - tt]);                      \
                fma2(dH[q], nWH, clo[7 - tt]);                      \
            }                                                       \
        }                                                           \
    }

__global__ void __launch_bounds__(NTHREADS, 3)
wavedec_kernel(const float* __restrict__ x, float* __restrict__ out) {
    __shared__ ulonglong2 s_a1[A1_CAP * 16];
    __shared__ ulonglong2 s_a2[A2_CAP * 16];

    const int tid  = threadIdx.x;
    const int f4   = tid & 15;    // float4 feature lane (64 floats = 16 float4)
    const int grp  = tid >> 4;    // 0..15, each group: 4 consecutive rows/pass
    const int tile = blockIdx.x;  // 0..31
    const int b    = blockIdx.y;  // 0..63

    // Reversed approx filter: out_a[i] = sum_t src[2i+t] * RLO[t]
    const float RLO[8] = {
         0.23037781330885523f,  0.7148465705525415f,   0.6308807679295904f,
        -0.02798376941698385f, -0.18703481171888114f,  0.030841381835986965f,
         0.032883011666982945f, -0.010597401784997278f };

    unsigned long long clo[8];
#pragma unroll
    for (int t = 0; t < 8; ++t)
        clo[t] = (unsigned long long)__float_as_uint(RLO[t]) * 0x100000001ull;

    const ulonglong2* __restrict__ xb4 =
        reinterpret_cast<const ulonglong2*>(x + (size_t)b * 4096 * 64);
    ulonglong2* __restrict__ ob4 =
        reinterpret_cast<ulonglong2*>(out + (size_t)b * 4096 * 64);

    const int g0 = 128 * tile - 42;  // global x row of local window origin

    // ---- Level 1: x (global) -> cA1 (smem) + cD1 (global) ----
#pragma unroll
    for (int pass = 0; pass < 2; ++pass) {
        const int i0 = pass * 64 + grp * 4;
        if (i0 < A1_ROWS) {
            unsigned long long aL[4] = {}, aH[4] = {}, dL[4] = {}, dH[4] = {};
            ulonglong2 v[14];
            const int r0 = g0 + 2 * i0;
            if (r0 >= 0 && r0 <= 4096 - 14) {
                const ulonglong2* p = xb4 + (size_t)r0 * 16 + f4;
#pragma unroll
                for (int t = 0; t < 14; ++t)
                    v[t] = p[t * 16];
            } else {
#pragma unroll
                for (int t = 0; t < 14; ++t) {
                    const int r = (r0 + t + 4096) & 4095;
                    v[t] = xb4[(size_t)r * 16 + f4];
                }
            }
            CONSUME_WINDOW
#pragma unroll
            for (int q = 0; q < 4; ++q) {
                const int i = i0 + q;          // max 83 < A1_CAP
                s_a1[i * 16 + f4] = make_ulonglong2(aL[q], aH[q]);
                if (i >= 18 && i < A1_ROWS)
                    ob4[(size_t)(2048 + 64 * tile + (i - 18)) * 16 + f4] =
                        make_ulonglong2(dL[q], dH[q]);
            }
        }
    }
    __syncthreads();

    // ---- Level 2: cA1 (smem) -> cA2 (smem) + cD2 (global) ----
    {
        const int i0 = grp * 4;
        if (i0 < A2_ROWS) {
            unsigned long long aL[4] = {}, aH[4] = {}, dL[4] = {}, dH[4] = {};
            ulonglong2 v[14];
            const ulonglong2* p = s_a1 + 2 * i0 * 16 + f4;
#pragma unroll
            for (int t = 0; t < 14; ++t)
                v[t] = p[t * 16];
            CONSUME_WINDOW
#pragma unroll
            for (int q = 0; q < 4; ++q) {
                const int i = i0 + q;          // max 39 < A2_CAP
                s_a2[i * 16 + f4] = make_ulonglong2(aL[q], aH[q]);
                if (i >= 6 && i < A2_ROWS)
                    ob4[(size_t)(1024 + 32 * tile + (i - 6)) * 16 + f4] =
                        make_ulonglong2(dL[q], dH[q]);
            }
        }
    }
    __syncthreads();

    // ---- Level 3: cA2 (smem) -> cA3 + cD3 (global) ----
    {
        const int i0 = grp * 4;
        if (i0 < 16) {
            unsigned long long aL[4] = {}, aH[4] = {}, dL[4] = {}, dH[4] = {};
            ulonglong2 v[14];
            const ulonglong2* p = s_a2 + 2 * i0 * 16 + f4;
#pragma unroll
            for (int t = 0; t < 14; ++t)
                v[t] = p[t * 16];
            CONSUME_WINDOW
#pragma unroll
            for (int q = 0; q < 4; ++q) {
                const int i = i0 + q;
                ob4[(size_t)(16 * tile + i) * 16 + f4] =
                    make_ulonglong2(aL[q], aH[q]);
                ob4[(size_t)(512 + 16 * tile + i) * 16 + f4] =
                    make_ulonglong2(dL[q], dH[q]);
            }
        }
    }
}

extern "C" void kernel_launch(void* const* d_in, const int* in_sizes, int n_in,
                              void* d_out, int out_size) {
    const float* x = (const float*)d_in[0];
    float* out = (float*)d_out;
    dim3 grid(32, 64);
    wavedec_kernel<<<grid, NTHREADS>>>(x, out);
}